// round 12
// baseline (speedup 1.0000x reference)
#include <cuda_runtime.h>
#include <math.h>

// ---------------- static scratch (no allocation allowed) ----------------
#define NMAX 100000
#define EMAX 1600000
#define GMAX 512
#define CMAX 16
#define VMAX 128

__device__ float g_hlin[NMAX * 16];   // layer input features (node_init / k_lin write)
__device__ float g_hout[NMAX * 16];   // GAT output (k_gat writes, k_lin/k_pool read)
__device__ int   g_cnt[NMAX];         // in-degree histogram
__device__ int   g_rowptr[NMAX + 1];  // CSR row pointers (by dst)
__device__ int   g_loc[EMAX];         // per-edge local offset within its dst bucket
__device__ int   g_col[EMAX];         // CSR columns = src node per edge
__device__ int   g_bsum[1024];        // fallback scan partials
__device__ unsigned long long g_lb[256]; // lookback scan: (value<<2)|flag
__device__ float g_embW[VMAX * 16];   // embedding @ W1 table
__device__ float g_psum[GMAX * CMAX]; // pooled sums
__device__ float g_pcnt[GMAX];        // pooled counts

__device__ __forceinline__ float lrelu(float x) { return x > 0.f ? x : 0.2f * x; }

// ---------------- precompute layer-1 table + zero scratch (fused) ----------------
__global__ void k_prep(const float* __restrict__ emb, const float* __restrict__ W1,
                       int V, int D, int H, int N, int G, int C)
{
    int gtid = blockIdx.x * blockDim.x + threadIdx.x;
    int gstr = gridDim.x * blockDim.x;
    for (int i = gtid; i < N; i += gstr) g_cnt[i] = 0;
    if (gtid < G * C) g_psum[gtid] = 0.f;
    if (gtid < G) g_pcnt[gtid] = 0.f;
    if (gtid < 256) g_lb[gtid] = 0ULL;

    if (blockIdx.x != 0) return;
    int tid = threadIdx.x;
    for (int t = tid; t < V * 16; t += blockDim.x) {
        int v = t >> 4, k = t & 15;
        float s = 0.f;
        if (k < H)
            for (int d = 0; d < D; d++) s += emb[v * D + d] * W1[d * H + k];
        g_embW[v * 16 + k] = s;
    }
}

// ---------------- argmax(x) per node + table lookup (warp per node, float4) ----------------
__global__ void k_node_init(const float* __restrict__ x, int N, int V)
{
    int wid = (blockIdx.x * blockDim.x + threadIdx.x) >> 5;
    int lid = threadIdx.x & 31;
    if (wid >= N) return;
    const float4* row = (const float4*)(x + (long long)wid * V);
    int V4 = V >> 2;
    float best = -INFINITY;
    int bidx = 0;
    for (int c = lid; c < V4; c += 32) {
        float4 f = row[c];
        int base = c * 4;
        if (f.x > best) { best = f.x; bidx = base; }
        if (f.y > best) { best = f.y; bidx = base + 1; }
        if (f.z > best) { best = f.z; bidx = base + 2; }
        if (f.w > best) { best = f.w; bidx = base + 3; }
    }
#pragma unroll
    for (int o = 16; o; o >>= 1) {
        float ov = __shfl_xor_sync(0xffffffffu, best, o);
        int   oi = __shfl_xor_sync(0xffffffffu, bidx, o);
        if (ov > best || (ov == best && oi < bidx)) { best = ov; bidx = oi; }
    }
    if (lid < 4)
        ((float4*)g_hlin)[wid * 4 + lid] = ((const float4*)g_embW)[bidx * 4 + lid];
}

// ---------------- CSR build ----------------
// hist also captures each edge's local offset (atomicAdd return) -> scatter needs no atomics
__global__ void k_hist(const int* __restrict__ ei, int E)
{
    int t = blockIdx.x * blockDim.x + threadIdx.x;
    int i0 = t * 2;
    if (i0 < E)     g_loc[i0]     = atomicAdd(&g_cnt[ei[E + i0]], 1);
    if (i0 + 1 < E) g_loc[i0 + 1] = atomicAdd(&g_cnt[ei[E + i0 + 1]], 1);
}

__device__ int block_exscan(int v, int* p_total)
{
    int lane = threadIdx.x & 31, w = threadIdx.x >> 5;
    int x = v;
#pragma unroll
    for (int o = 1; o < 32; o <<= 1) {
        int y = __shfl_up_sync(0xffffffffu, x, o);
        if (lane >= o) x += y;
    }
    __shared__ int ws[32];
    if (lane == 31) ws[w] = x;
    __syncthreads();
    int nw = (blockDim.x + 31) >> 5;
    if (w == 0) {
        int z = (lane < nw) ? ws[lane] : 0;
#pragma unroll
        for (int o = 1; o < 32; o <<= 1) {
            int y = __shfl_up_sync(0xffffffffu, z, o);
            if (lane >= o) z += y;
        }
        ws[lane] = z;
    }
    __syncthreads();
    int off = (w > 0) ? ws[w - 1] : 0;
    int total = ws[nw - 1];
    if (p_total) *p_total = total;
    return off + x - v;
}

// single-kernel exclusive scan via warp-parallel decoupled lookback (grid <= 148)
__global__ void __launch_bounds__(1024) k_scan_lb(int N)
{
    int b = blockIdx.x;
    int idx = b * 1024 + threadIdx.x;
    int v = (idx < N) ? g_cnt[idx] : 0;
    int tot;
    int ex = block_exscan(v, &tot);
    __shared__ int s_off;
    int lane = threadIdx.x & 31;
    if (threadIdx.x < 32) {
        if (b == 0) {
            if (lane == 0) {
                atomicExch(&g_lb[0], ((unsigned long long)(unsigned)tot << 2) | 2ULL);
                s_off = 0;
            }
        } else {
            if (lane == 0)
                atomicExch(&g_lb[b], ((unsigned long long)(unsigned)tot << 2) | 1ULL);
            int off = 0;
            int base = b - 1;
            for (;;) {
                int i = base - lane;
                unsigned f = 2; int val = 0;
                if (i >= 0) {
                    unsigned long long u = atomicAdd(&g_lb[i], 0ULL);
                    f = (unsigned)(u & 3ULL);
                    val = (int)(unsigned)(u >> 2);
                }
                if (__any_sync(0xffffffffu, f == 0)) continue;
                unsigned doneMask = __ballot_sync(0xffffffffu, f == 2);
                if (doneMask) {
                    int firstDone = __ffs(doneMask) - 1;
                    int contrib = (lane <= firstDone) ? val : 0;
#pragma unroll
                    for (int o = 16; o; o >>= 1)
                        contrib += __shfl_xor_sync(0xffffffffu, contrib, o);
                    off += contrib;
                    break;
                } else {
                    int contrib = val;
#pragma unroll
                    for (int o = 16; o; o >>= 1)
                        contrib += __shfl_xor_sync(0xffffffffu, contrib, o);
                    off += contrib;
                    base -= 32;
                }
            }
            if (lane == 0) {
                atomicExch(&g_lb[b], ((unsigned long long)(unsigned)(off + tot) << 2) | 2ULL);
                s_off = off;
            }
        }
    }
    __syncthreads();
    int off = s_off;
    if (idx < N) g_rowptr[idx] = off + ex;
    if (b == gridDim.x - 1 && threadIdx.x == 0) g_rowptr[N] = off + tot;
}

// fallback 3-pass scan (only if grid would exceed resident blocks)
__global__ void k_scan1(int N)
{
    int idx = blockIdx.x * 1024 + threadIdx.x;
    int v = (idx < N) ? g_cnt[idx] : 0;
    int tot;
    block_exscan(v, &tot);
    if (threadIdx.x == 0) g_bsum[blockIdx.x] = tot;
}
__global__ void k_scan2(int B, int N)
{
    int v = ((int)threadIdx.x < B) ? g_bsum[threadIdx.x] : 0;
    int tot;
    int ex = block_exscan(v, &tot);
    if ((int)threadIdx.x < B) g_bsum[threadIdx.x] = ex;
    if (threadIdx.x == 0) g_rowptr[N] = tot;
}
__global__ void k_scan3(int N)
{
    int idx = blockIdx.x * 1024 + threadIdx.x;
    int v = (idx < N) ? g_cnt[idx] : 0;
    int ex = block_exscan(v, nullptr) + g_bsum[blockIdx.x];
    if (idx < N) g_rowptr[idx] = ex;
}

// atomic-free scatter: position = rowptr[dst] + loc[e]
__global__ void k_scatter(const int* __restrict__ ei, int E)
{
    int e = blockIdx.x * blockDim.x + threadIdx.x;
    if (e < E) {
        int d = ei[E + e];
        g_col[g_rowptr[d] + g_loc[e]] = ei[e];
    }
}

// ---------------- GAT layer: warp per destination node ----------------
// alpha_src recomputed IN-REGISTER from the gathered feature row (dot with a_src
// via intra-quad butterfly) -> no g_as array, no random 4B gathers.
// Unshifted softmax (|e| << 88, shift-invariant -> identical result).
// Lane layout: quad q = lid&3 owns features [4q,4q+4); e8 = lid>>2 selects edge slot.
template <int F, bool RELU>
__global__ void __launch_bounds__(256) k_gat(const float* __restrict__ bias,
                                             const float* __restrict__ av,
                                             const float* __restrict__ dv, int N)
{
    int wid = (blockIdx.x * blockDim.x + threadIdx.x) >> 5;
    int lid = threadIdx.x & 31;
    if (wid >= N) return;
    int n = wid;
    int beg = g_rowptr[n], end = g_rowptr[n + 1];

    int q = lid & 3, e8 = lid >> 2;
    int k0 = q * 4;
    float4 sa4, sd4;
    sa4.x = (k0 + 0 < F) ? av[k0 + 0] : 0.f;
    sa4.y = (k0 + 1 < F) ? av[k0 + 1] : 0.f;
    sa4.z = (k0 + 2 < F) ? av[k0 + 2] : 0.f;
    sa4.w = (k0 + 3 < F) ? av[k0 + 3] : 0.f;
    sd4.x = (k0 + 0 < F) ? dv[k0 + 0] : 0.f;
    sd4.y = (k0 + 1 < F) ? dv[k0 + 1] : 0.f;
    sd4.z = (k0 + 2 < F) ? dv[k0 + 2] : 0.f;
    sd4.w = (k0 + 3 < F) ? dv[k0 + 3] : 0.f;

    const float4* h4 = (const float4*)g_hlin;

    // self row: alpha_src(n) and alpha_dst(n) via intra-quad butterfly
    float4 hself = h4[n * 4 + q];
    float ps = hself.x * sa4.x + hself.y * sa4.y + hself.z * sa4.z + hself.w * sa4.w;
    float pd = hself.x * sd4.x + hself.y * sd4.y + hself.z * sd4.z + hself.w * sd4.w;
    ps += __shfl_xor_sync(0xffffffffu, ps, 1); ps += __shfl_xor_sync(0xffffffffu, ps, 2);
    pd += __shfl_xor_sync(0xffffffffu, pd, 1); pd += __shfl_xor_sync(0xffffffffu, pd, 2);
    float adn = pd;
    float p_self = __expf(lrelu(ps + adn));

    float den = (lid == 0) ? p_self : 0.f;
    float4 acc = make_float4(0.f, 0.f, 0.f, 0.f);
    if (e8 == 0) {   // self-loop contribution (counted once after e8-reduction)
        acc.x = p_self * hself.x; acc.y = p_self * hself.y;
        acc.z = p_self * hself.z; acc.w = p_self * hself.w;
    }

    // 32 edges per outer step; each quad handles 4 edges (slots e8, 8+e8, 16+e8, 24+e8)
    for (int c = beg; c < end; c += 32) {
        float4 hv[4];
        bool vld[4];
#pragma unroll
        for (int u = 0; u < 4; u++) {
            int j = c + u * 8 + e8;
            vld[u] = (j < end);
            int s = vld[u] ? g_col[j] : n;     // dummy self row when invalid
            hv[u] = h4[s * 4 + q];             // 4 independent 64B/quad gathers in flight
        }
#pragma unroll
        for (int u = 0; u < 4; u++) {
            float part = hv[u].x * sa4.x + hv[u].y * sa4.y
                       + hv[u].z * sa4.z + hv[u].w * sa4.w;
            part += __shfl_xor_sync(0xffffffffu, part, 1);
            part += __shfl_xor_sync(0xffffffffu, part, 2);
            float p = vld[u] ? __expf(lrelu(part + adn)) : 0.f;
            if (q == 0) den += p;
            acc.x += p * hv[u].x; acc.y += p * hv[u].y;
            acc.z += p * hv[u].z; acc.w += p * hv[u].w;
        }
    }
#pragma unroll
    for (int o = 16; o; o >>= 1) den += __shfl_xor_sync(0xffffffffu, den, o);
#pragma unroll
    for (int o = 4; o <= 16; o <<= 1) {
        acc.x += __shfl_xor_sync(0xffffffffu, acc.x, o);
        acc.y += __shfl_xor_sync(0xffffffffu, acc.y, o);
        acc.z += __shfl_xor_sync(0xffffffffu, acc.z, o);
        acc.w += __shfl_xor_sync(0xffffffffu, acc.w, o);
    }

    if (lid < 4) {
        float inv = 1.f / den;
        float o0 = (k0 + 0 < F) ? acc.x * inv + bias[k0 + 0] : 0.f;
        float o1 = (k0 + 1 < F) ? acc.y * inv + bias[k0 + 1] : 0.f;
        float o2 = (k0 + 2 < F) ? acc.z * inv + bias[k0 + 2] : 0.f;
        float o3 = (k0 + 3 < F) ? acc.w * inv + bias[k0 + 3] : 0.f;
        if (RELU) {
            o0 = fmaxf(o0, 0.f); o1 = fmaxf(o1, 0.f);
            o2 = fmaxf(o2, 0.f); o3 = fmaxf(o3, 0.f);
        }
        ((float4*)g_hout)[n * 4 + q] = make_float4(o0, o1, o2, o3);
    }
}

// ---------------- inter-layer linear: h@W (alphas now computed in k_gat) ----------------
template <int FOUT>
__global__ void k_lin(const float* __restrict__ W, int N)
{
    __shared__ float sW[16 * FOUT];
    for (int i = threadIdx.x; i < 16 * FOUT; i += blockDim.x) sW[i] = W[i];
    __syncthreads();
    int n = blockIdx.x * blockDim.x + threadIdx.x;
    if (n >= N) return;
    float h[16];
    const float4* hp = (const float4*)(g_hout + n * 16);
#pragma unroll
    for (int qq = 0; qq < 4; qq++) {
        float4 f = hp[qq];
        h[qq * 4] = f.x; h[qq * 4 + 1] = f.y; h[qq * 4 + 2] = f.z; h[qq * 4 + 3] = f.w;
    }
    float out[16];
#pragma unroll
    for (int kk = 0; kk < FOUT; kk++) {
        float s = 0.f;
#pragma unroll
        for (int j = 0; j < 16; j++) s += h[j] * sW[j * FOUT + kk];
        out[kk] = s;
    }
#pragma unroll
    for (int kk = FOUT; kk < 16; kk++) out[kk] = 0.f;
    float4* op = (float4*)(g_hlin + n * 16);
#pragma unroll
    for (int qq = 0; qq < 4; qq++)
        op[qq] = make_float4(out[qq * 4], out[qq * 4 + 1], out[qq * 4 + 2], out[qq * 4 + 3]);
}

// ---------------- global mean pool (warp-uniform reduction) + softmax ----------------
template <int C>
__global__ void k_pool(const int* __restrict__ batch, int N)
{
    int n = blockIdx.x * blockDim.x + threadIdx.x;
    bool valid = n < N;
    int g = valid ? batch[n] : -1;
    float v[C];
#pragma unroll
    for (int k = 0; k < C; k++) v[k] = valid ? g_hout[n * 16 + k] : 0.f;
    int g0 = __shfl_sync(0xffffffffu, g, 0);
    bool uni = __all_sync(0xffffffffu, g == g0);
    if (uni) {   // batch sorted -> common case: whole warp same graph
#pragma unroll
        for (int k = 0; k < C; k++)
#pragma unroll
            for (int o = 16; o; o >>= 1) v[k] += __shfl_xor_sync(0xffffffffu, v[k], o);
        if ((threadIdx.x & 31) == 0 && g0 >= 0) {
#pragma unroll
            for (int k = 0; k < C; k++) atomicAdd(&g_psum[g0 * C + k], v[k]);
            atomicAdd(&g_pcnt[g0], 32.f);
        }
    } else if (valid) {
#pragma unroll
        for (int k = 0; k < C; k++) atomicAdd(&g_psum[g * C + k], v[k]);
        atomicAdd(&g_pcnt[g], 1.f);
    }
}

__global__ void k_softmax(float* __restrict__ out, int G, int C)
{
    int wid = (blockIdx.x * blockDim.x + threadIdx.x) >> 5;
    int lid = threadIdx.x & 31;
    if (wid >= G) return;
    float val = (lid < C) ? g_psum[wid * C + lid] / fmaxf(g_pcnt[wid], 1.f) : -INFINITY;
    float mm = val;
#pragma unroll
    for (int o = 16; o; o >>= 1) mm = fmaxf(mm, __shfl_xor_sync(0xffffffffu, mm, o));
    float p = (lid < C) ? __expf(val - mm) : 0.f;
    float s = p;
#pragma unroll
    for (int o = 16; o; o >>= 1) s += __shfl_xor_sync(0xffffffffu, s, o);
    if (lid < C) out[wid * C + lid] = p / s;
}

// ---------------- launch ----------------
extern "C" void kernel_launch(void* const* d_in, const int* in_sizes, int n_in,
                              void* d_out, int out_size)
{
    const float* x    = (const float*)d_in[0];
    const int*   ei   = (const int*)d_in[1];
    const int*   batch= (const int*)d_in[2];
    const float* emb  = (const float*)d_in[3];
    const float* W1   = (const float*)d_in[4];
    const float* as1  = (const float*)d_in[5];
    const float* ad1  = (const float*)d_in[6];
    const float* b1   = (const float*)d_in[7];
    const float* W2   = (const float*)d_in[8];
    const float* as2  = (const float*)d_in[9];
    const float* ad2  = (const float*)d_in[10];
    const float* b2   = (const float*)d_in[11];
    const float* W3   = (const float*)d_in[12];
    const float* as3  = (const float*)d_in[13];
    const float* ad3  = (const float*)d_in[14];
    const float* b3   = (const float*)d_in[15];
    float* out = (float*)d_out;

    int H = in_sizes[5];                 // 16
    int C = in_sizes[13];                // 10
    int D = in_sizes[4] / H;             // 50
    int V = in_sizes[3] / D;             // 128
    int N = in_sizes[0] / V;             // 100000
    int E = in_sizes[1] / 2;             // 1600000
    int G = out_size / C;                // 512

    static cudaStream_t s_side = nullptr;
    static cudaEvent_t evFork = nullptr, evJoin = nullptr;
    if (!s_side) {
        cudaStreamCreateWithFlags(&s_side, cudaStreamNonBlocking);
        cudaEventCreateWithFlags(&evFork, cudaEventDisableTiming);
        cudaEventCreateWithFlags(&evJoin, cudaEventDisableTiming);
    }

    // table + zero scratch
    k_prep<<<200, 256>>>(emb, W1, V, D, H, N, G, C);

    // fork: CSR build on side stream, node_init on main stream
    cudaEventRecord(evFork, 0);
    cudaStreamWaitEvent(s_side, evFork, 0);

    k_hist<<<(E / 2 + 255) / 256, 256, 0, s_side>>>(ei, E);
    int B = (N + 1023) / 1024;
    if (B <= 148) {
        k_scan_lb<<<B, 1024, 0, s_side>>>(N);
    } else {
        k_scan1<<<B, 1024, 0, s_side>>>(N);
        k_scan2<<<1, 1024, 0, s_side>>>(B, N);
        k_scan3<<<B, 1024, 0, s_side>>>(N);
    }
    k_scatter<<<(E + 255) / 256, 256, 0, s_side>>>(ei, E);
    cudaEventRecord(evJoin, s_side);

    int niBlocks = (N * 32 + 255) / 256;
    k_node_init<<<niBlocks, 256>>>(x, N, V);

    cudaStreamWaitEvent(0, evJoin, 0);

    // 3 GAT layers (in-register alpha) with separate inter-layer linears
    int gatBlocks = (N * 32 + 255) / 256;
    k_gat<16, true ><<<gatBlocks, 256>>>(b1, as1, ad1, N);
    k_lin<16><<<(N + 255) / 256, 256>>>(W2, N);
    k_gat<16, true ><<<gatBlocks, 256>>>(b2, as2, ad2, N);
    k_lin<10><<<(N + 255) / 256, 256>>>(W3, N);
    k_gat<10, false><<<gatBlocks, 256>>>(b3, as3, ad3, N);

    // pool + softmax
    k_pool<10><<<(N + 255) / 256, 256>>>(batch, N);
    k_softmax<<<(G * 32 + 255) / 256, 256>>>(out, G, C);
}

// round 13
// speedup vs baseline: 1.1175x; 1.1175x over previous
#include <cuda_runtime.h>
#include <math.h>

// ---------------- static scratch (no allocation allowed) ----------------
#define NMAX 100000
#define EMAX 1600000
#define GMAX 512
#define CMAX 16
#define VMAX 128

__device__ float g_hlin[NMAX * 16];   // layer input features (node_init / k_lin write)
__device__ float g_hout[NMAX * 16];   // GAT output (k_gat writes, k_lin/k_pool read)
__device__ float g_as[NMAX];          // alpha_src per node
__device__ float g_ad[NMAX];          // alpha_dst per node
__device__ int   g_cnt[NMAX];         // in-degree histogram
__device__ int   g_rowptr[NMAX + 1];  // CSR row pointers (by dst)
__device__ int   g_loc[EMAX];         // per-edge local offset within its dst bucket
__device__ int   g_col[EMAX];         // CSR columns = src node per edge
__device__ int   g_bsum[1024];        // fallback scan partials
__device__ unsigned long long g_lb[256]; // lookback scan: (value<<2)|flag
__device__ float g_embW[VMAX * 16];   // embedding @ W1 table
__device__ float g_tabs[VMAX];        // embW @ a_src1
__device__ float g_tabd[VMAX];        // embW @ a_dst1
__device__ float g_psum[GMAX * CMAX]; // pooled sums
__device__ float g_pcnt[GMAX];        // pooled counts

__device__ __forceinline__ float lrelu(float x) { return x > 0.f ? x : 0.2f * x; }

// ---------------- precompute layer-1 tables + zero scratch (fused) ----------------
__global__ void k_prep(const float* __restrict__ emb, const float* __restrict__ W1,
                       const float* __restrict__ a_s, const float* __restrict__ a_d,
                       int V, int D, int H, int N, int G, int C)
{
    int gtid = blockIdx.x * blockDim.x + threadIdx.x;
    int gstr = gridDim.x * blockDim.x;
    for (int i = gtid; i < N; i += gstr) g_cnt[i] = 0;
    if (gtid < G * C) g_psum[gtid] = 0.f;
    if (gtid < G) g_pcnt[gtid] = 0.f;
    if (gtid < 256) g_lb[gtid] = 0ULL;

    if (blockIdx.x != 0) return;
    int tid = threadIdx.x;
    for (int t = tid; t < V * 16; t += blockDim.x) {
        int v = t >> 4, k = t & 15;
        float s = 0.f;
        if (k < H)
            for (int d = 0; d < D; d++) s += emb[v * D + d] * W1[d * H + k];
        g_embW[v * 16 + k] = s;
    }
    __syncthreads();
    for (int v = tid; v < V; v += blockDim.x) {
        float ss = 0.f, sd = 0.f;
        for (int k = 0; k < H; k++) {
            float e = g_embW[v * 16 + k];
            ss += e * a_s[k];
            sd += e * a_d[k];
        }
        g_tabs[v] = ss;
        g_tabd[v] = sd;
    }
}

// ---------------- argmax(x) per node + table lookup (warp per node, float4) ----------------
__global__ void k_node_init(const float* __restrict__ x, int N, int V)
{
    int wid = (blockIdx.x * blockDim.x + threadIdx.x) >> 5;
    int lid = threadIdx.x & 31;
    if (wid >= N) return;
    const float4* row = (const float4*)(x + (long long)wid * V);
    int V4 = V >> 2;
    float best = -INFINITY;
    int bidx = 0;
    for (int c = lid; c < V4; c += 32) {
        float4 f = row[c];
        int base = c * 4;
        if (f.x > best) { best = f.x; bidx = base; }
        if (f.y > best) { best = f.y; bidx = base + 1; }
        if (f.z > best) { best = f.z; bidx = base + 2; }
        if (f.w > best) { best = f.w; bidx = base + 3; }
    }
#pragma unroll
    for (int o = 16; o; o >>= 1) {
        float ov = __shfl_xor_sync(0xffffffffu, best, o);
        int   oi = __shfl_xor_sync(0xffffffffu, bidx, o);
        if (ov > best || (ov == best && oi < bidx)) { best = ov; bidx = oi; }
    }
    if (lid < 4)
        ((float4*)g_hlin)[wid * 4 + lid] = ((const float4*)g_embW)[bidx * 4 + lid];
    if (lid == 0) { g_as[wid] = g_tabs[bidx]; g_ad[wid] = g_tabd[bidx]; }
}

// ---------------- CSR build ----------------
// hist captures each edge's local offset (atomicAdd return) -> scatter needs no atomics
__global__ void k_hist(const int* __restrict__ ei, int E)
{
    int t = blockIdx.x * blockDim.x + threadIdx.x;
    int i0 = t * 2;
    if (i0 < E)     g_loc[i0]     = atomicAdd(&g_cnt[ei[E + i0]], 1);
    if (i0 + 1 < E) g_loc[i0 + 1] = atomicAdd(&g_cnt[ei[E + i0 + 1]], 1);
}

__device__ int block_exscan(int v, int* p_total)
{
    int lane = threadIdx.x & 31, w = threadIdx.x >> 5;
    int x = v;
#pragma unroll
    for (int o = 1; o < 32; o <<= 1) {
        int y = __shfl_up_sync(0xffffffffu, x, o);
        if (lane >= o) x += y;
    }
    __shared__ int ws[32];
    if (lane == 31) ws[w] = x;
    __syncthreads();
    int nw = (blockDim.x + 31) >> 5;
    if (w == 0) {
        int z = (lane < nw) ? ws[lane] : 0;
#pragma unroll
        for (int o = 1; o < 32; o <<= 1) {
            int y = __shfl_up_sync(0xffffffffu, z, o);
            if (lane >= o) z += y;
        }
        ws[lane] = z;
    }
    __syncthreads();
    int off = (w > 0) ? ws[w - 1] : 0;
    int total = ws[nw - 1];
    if (p_total) *p_total = total;
    return off + x - v;
}

// single-kernel exclusive scan via warp-parallel decoupled lookback (grid <= 148)
__global__ void __launch_bounds__(1024) k_scan_lb(int N)
{
    int b = blockIdx.x;
    int idx = b * 1024 + threadIdx.x;
    int v = (idx < N) ? g_cnt[idx] : 0;
    int tot;
    int ex = block_exscan(v, &tot);
    __shared__ int s_off;
    int lane = threadIdx.x & 31;
    if (threadIdx.x < 32) {
        if (b == 0) {
            if (lane == 0) {
                atomicExch(&g_lb[0], ((unsigned long long)(unsigned)tot << 2) | 2ULL);
                s_off = 0;
            }
        } else {
            if (lane == 0)
                atomicExch(&g_lb[b], ((unsigned long long)(unsigned)tot << 2) | 1ULL);
            int off = 0;
            int base = b - 1;
            for (;;) {
                int i = base - lane;
                unsigned f = 2; int val = 0;
                if (i >= 0) {
                    unsigned long long u = atomicAdd(&g_lb[i], 0ULL);
                    f = (unsigned)(u & 3ULL);
                    val = (int)(unsigned)(u >> 2);
                }
                if (__any_sync(0xffffffffu, f == 0)) continue;
                unsigned doneMask = __ballot_sync(0xffffffffu, f == 2);
                if (doneMask) {
                    int firstDone = __ffs(doneMask) - 1;
                    int contrib = (lane <= firstDone) ? val : 0;
#pragma unroll
                    for (int o = 16; o; o >>= 1)
                        contrib += __shfl_xor_sync(0xffffffffu, contrib, o);
                    off += contrib;
                    break;
                } else {
                    int contrib = val;
#pragma unroll
                    for (int o = 16; o; o >>= 1)
                        contrib += __shfl_xor_sync(0xffffffffu, contrib, o);
                    off += contrib;
                    base -= 32;
                }
            }
            if (lane == 0) {
                atomicExch(&g_lb[b], ((unsigned long long)(unsigned)(off + tot) << 2) | 2ULL);
                s_off = off;
            }
        }
    }
    __syncthreads();
    int off = s_off;
    if (idx < N) g_rowptr[idx] = off + ex;
    if (b == gridDim.x - 1 && threadIdx.x == 0) g_rowptr[N] = off + tot;
}

// fallback 3-pass scan (only if grid would exceed resident blocks)
__global__ void k_scan1(int N)
{
    int idx = blockIdx.x * 1024 + threadIdx.x;
    int v = (idx < N) ? g_cnt[idx] : 0;
    int tot;
    block_exscan(v, &tot);
    if (threadIdx.x == 0) g_bsum[blockIdx.x] = tot;
}
__global__ void k_scan2(int B, int N)
{
    int v = ((int)threadIdx.x < B) ? g_bsum[threadIdx.x] : 0;
    int tot;
    int ex = block_exscan(v, &tot);
    if ((int)threadIdx.x < B) g_bsum[threadIdx.x] = ex;
    if (threadIdx.x == 0) g_rowptr[N] = tot;
}
__global__ void k_scan3(int N)
{
    int idx = blockIdx.x * 1024 + threadIdx.x;
    int v = (idx < N) ? g_cnt[idx] : 0;
    int ex = block_exscan(v, nullptr) + g_bsum[blockIdx.x];
    if (idx < N) g_rowptr[idx] = ex;
}

// atomic-free scatter: position = rowptr[dst] + loc[e]
__global__ void k_scatter(const int* __restrict__ ei, int E)
{
    int e = blockIdx.x * blockDim.x + threadIdx.x;
    if (e < E) {
        int d = ei[E + e];
        g_col[g_rowptr[d] + g_loc[e]] = ei[e];
    }
}

// ---------------- GAT layer: warp per destination node (R11-exact) ----------------
// Unshifted softmax (|e| << 88, shift-invariant -> identical result).
template <int F, bool RELU>
__global__ void k_gat(const float* __restrict__ bias, int N)
{
    int wid = (blockIdx.x * blockDim.x + threadIdx.x) >> 5;
    int lid = threadIdx.x & 31;
    if (wid >= N) return;
    int n = wid;
    int beg = g_rowptr[n], end = g_rowptr[n + 1];
    float adn = g_ad[n];
    float p_self = __expf(lrelu(g_as[n] + adn));

    int q = lid & 3, e8 = lid >> 2;
    const float4* h4 = (const float4*)g_hlin;

    float den = (lid == 0) ? p_self : 0.f;
    float4 acc = make_float4(0.f, 0.f, 0.f, 0.f);
    if (e8 == 0) {   // self-loop contribution
        float4 hv = h4[n * 4 + q];
        acc.x = p_self * hv.x; acc.y = p_self * hv.y;
        acc.z = p_self * hv.z; acc.w = p_self * hv.w;
    }

    for (int c = beg; c < end; c += 32) {
        int j = c + lid;
        int s = 0;
        float p = 0.f;
        if (j < end) {
            s = g_col[j];
            p = __expf(lrelu(g_as[s] + adn));
        }
        den += p;
        int cnt = min(32, end - c);
        for (int jj = 0; jj < cnt; jj += 8) {
            int lane = jj + e8;                 // lane >= cnt has p=0 -> harmless
            int   ss = __shfl_sync(0xffffffffu, s, lane);
            float pp = __shfl_sync(0xffffffffu, p, lane);
            float4 hv = h4[ss * 4 + q];         // 64B coalesced per 4-lane group
            acc.x += pp * hv.x; acc.y += pp * hv.y;
            acc.z += pp * hv.z; acc.w += pp * hv.w;
        }
    }
#pragma unroll
    for (int o = 16; o; o >>= 1) den += __shfl_xor_sync(0xffffffffu, den, o);
#pragma unroll
    for (int o = 4; o <= 16; o <<= 1) {
        acc.x += __shfl_xor_sync(0xffffffffu, acc.x, o);
        acc.y += __shfl_xor_sync(0xffffffffu, acc.y, o);
        acc.z += __shfl_xor_sync(0xffffffffu, acc.z, o);
        acc.w += __shfl_xor_sync(0xffffffffu, acc.w, o);
    }

    if (lid < 4) {
        float inv = 1.f / den;
        int k0 = q * 4;
        float o0 = (k0 + 0 < F) ? acc.x * inv + bias[k0 + 0] : 0.f;
        float o1 = (k0 + 1 < F) ? acc.y * inv + bias[k0 + 1] : 0.f;
        float o2 = (k0 + 2 < F) ? acc.z * inv + bias[k0 + 2] : 0.f;
        float o3 = (k0 + 3 < F) ? acc.w * inv + bias[k0 + 3] : 0.f;
        if (RELU) {
            o0 = fmaxf(o0, 0.f); o1 = fmaxf(o1, 0.f);
            o2 = fmaxf(o2, 0.f); o3 = fmaxf(o3, 0.f);
        }
        ((float4*)g_hout)[n * 4 + q] = make_float4(o0, o1, o2, o3);
    }
}

// ---------------- inter-layer linear: h@W, alpha_src, alpha_dst ----------------
template <int FOUT>
__global__ void k_lin(const float* __restrict__ W, const float* __restrict__ av,
                      const float* __restrict__ dv, int N)
{
    __shared__ float sW[16 * FOUT];
    __shared__ float sa[FOUT], sd[FOUT];
    for (int i = threadIdx.x; i < 16 * FOUT; i += blockDim.x) sW[i] = W[i];
    if (threadIdx.x < FOUT) { sa[threadIdx.x] = av[threadIdx.x]; sd[threadIdx.x] = dv[threadIdx.x]; }
    __syncthreads();
    int n = blockIdx.x * blockDim.x + threadIdx.x;
    if (n >= N) return;
    float h[16];
    const float4* hp = (const float4*)(g_hout + n * 16);
#pragma unroll
    for (int qq = 0; qq < 4; qq++) {
        float4 f = hp[qq];
        h[qq * 4] = f.x; h[qq * 4 + 1] = f.y; h[qq * 4 + 2] = f.z; h[qq * 4 + 3] = f.w;
    }
    float out[16];
    float as_ = 0.f, ad_ = 0.f;
#pragma unroll
    for (int kk = 0; kk < FOUT; kk++) {
        float s = 0.f;
#pragma unroll
        for (int j = 0; j < 16; j++) s += h[j] * sW[j * FOUT + kk];
        out[kk] = s;
        as_ += s * sa[kk];
        ad_ += s * sd[kk];
    }
#pragma unroll
    for (int kk = FOUT; kk < 16; kk++) out[kk] = 0.f;
    float4* op = (float4*)(g_hlin + n * 16);
#pragma unroll
    for (int qq = 0; qq < 4; qq++)
        op[qq] = make_float4(out[qq * 4], out[qq * 4 + 1], out[qq * 4 + 2], out[qq * 4 + 3]);
    g_as[n] = as_;
    g_ad[n] = ad_;
}

// ---------------- global mean pool (warp-uniform reduction) + softmax ----------------
template <int C>
__global__ void k_pool(const int* __restrict__ batch, int N)
{
    int n = blockIdx.x * blockDim.x + threadIdx.x;
    bool valid = n < N;
    int g = valid ? batch[n] : -1;
    float v[C];
#pragma unroll
    for (int k = 0; k < C; k++) v[k] = valid ? g_hout[n * 16 + k] : 0.f;
    int g0 = __shfl_sync(0xffffffffu, g, 0);
    bool uni = __all_sync(0xffffffffu, g == g0);
    if (uni) {   // batch sorted -> common case: whole warp same graph
#pragma unroll
        for (int k = 0; k < C; k++)
#pragma unroll
            for (int o = 16; o; o >>= 1) v[k] += __shfl_xor_sync(0xffffffffu, v[k], o);
        if ((threadIdx.x & 31) == 0 && g0 >= 0) {
#pragma unroll
            for (int k = 0; k < C; k++) atomicAdd(&g_psum[g0 * C + k], v[k]);
            atomicAdd(&g_pcnt[g0], 32.f);
        }
    } else if (valid) {
#pragma unroll
        for (int k = 0; k < C; k++) atomicAdd(&g_psum[g * C + k], v[k]);
        atomicAdd(&g_pcnt[g], 1.f);
    }
}

__global__ void k_softmax(float* __restrict__ out, int G, int C)
{
    int wid = (blockIdx.x * blockDim.x + threadIdx.x) >> 5;
    int lid = threadIdx.x & 31;
    if (wid >= G) return;
    float val = (lid < C) ? g_psum[wid * C + lid] / fmaxf(g_pcnt[wid], 1.f) : -INFINITY;
    float mm = val;
#pragma unroll
    for (int o = 16; o; o >>= 1) mm = fmaxf(mm, __shfl_xor_sync(0xffffffffu, mm, o));
    float p = (lid < C) ? __expf(val - mm) : 0.f;
    float s = p;
#pragma unroll
    for (int o = 16; o; o >>= 1) s += __shfl_xor_sync(0xffffffffu, s, o);
    if (lid < C) out[wid * C + lid] = p / s;
}

// ---------------- launch ----------------
extern "C" void kernel_launch(void* const* d_in, const int* in_sizes, int n_in,
                              void* d_out, int out_size)
{
    const float* x    = (const float*)d_in[0];
    const int*   ei   = (const int*)d_in[1];
    const int*   batch= (const int*)d_in[2];
    const float* emb  = (const float*)d_in[3];
    const float* W1   = (const float*)d_in[4];
    const float* as1  = (const float*)d_in[5];
    const float* ad1  = (const float*)d_in[6];
    const float* b1   = (const float*)d_in[7];
    const float* W2   = (const float*)d_in[8];
    const float* as2  = (const float*)d_in[9];
    const float* ad2  = (const float*)d_in[10];
    const float* b2   = (const float*)d_in[11];
    const float* W3   = (const float*)d_in[12];
    const float* as3  = (const float*)d_in[13];
    const float* ad3  = (const float*)d_in[14];
    const float* b3   = (const float*)d_in[15];
    float* out = (float*)d_out;

    int H = in_sizes[5];                 // 16
    int C = in_sizes[13];                // 10
    int D = in_sizes[4] / H;             // 50
    int V = in_sizes[3] / D;             // 128
    int N = in_sizes[0] / V;             // 100000
    int E = in_sizes[1] / 2;             // 1600000
    int G = out_size / C;                // 512

    static cudaStream_t s_side = nullptr;
    static cudaEvent_t evFork = nullptr, evJoin = nullptr;
    if (!s_side) {
        cudaStreamCreateWithFlags(&s_side, cudaStreamNonBlocking);
        cudaEventCreateWithFlags(&evFork, cudaEventDisableTiming);
        cudaEventCreateWithFlags(&evJoin, cudaEventDisableTiming);
    }

    // tables + zero scratch
    k_prep<<<200, 256>>>(emb, W1, as1, ad1, V, D, H, N, G, C);

    // fork: CSR build on side stream, node_init on main stream
    cudaEventRecord(evFork, 0);
    cudaStreamWaitEvent(s_side, evFork, 0);

    k_hist<<<(E / 2 + 255) / 256, 256, 0, s_side>>>(ei, E);
    int B = (N + 1023) / 1024;
    if (B <= 148) {
        k_scan_lb<<<B, 1024, 0, s_side>>>(N);
    } else {
        k_scan1<<<B, 1024, 0, s_side>>>(N);
        k_scan2<<<1, 1024, 0, s_side>>>(B, N);
        k_scan3<<<B, 1024, 0, s_side>>>(N);
    }
    k_scatter<<<(E + 255) / 256, 256, 0, s_side>>>(ei, E);
    cudaEventRecord(evJoin, s_side);

    int niBlocks = (N * 32 + 255) / 256;
    k_node_init<<<niBlocks, 256>>>(x, N, V);

    cudaStreamWaitEvent(0, evJoin, 0);

    // 3 GAT layers (R11-exact) with separate inter-layer linears
    int gatBlocks = (N * 32 + 255) / 256;
    k_gat<16, true ><<<gatBlocks, 256>>>(b1, N);
    k_lin<16><<<(N + 255) / 256, 256>>>(W2, as2, ad2, N);
    k_gat<16, true ><<<gatBlocks, 256>>>(b2, N);
    k_lin<10><<<(N + 255) / 256, 256>>>(W3, as3, ad3, N);
    k_gat<10, false><<<gatBlocks, 256>>>(b3, N);

    // pool + softmax
    k_pool<10><<<(N + 255) / 256, 256>>>(batch, N);
    k_softmax<<<(G * 32 + 255) / 256, 256>>>(out, G, C);
}